// round 8
// baseline (speedup 1.0000x reference)
#include <cuda_runtime.h>
#include <cuda_bf16.h>

#define BSZ 8
#define CSZ 19
#define HSZ 256
#define WSZ 256
#define HW  (HSZ * WSZ)
#define INF_F 1.0e6f

// 2 MB scratch for squared per-row distances  [B][H][W]
__device__ float g_g2[BSZ * HSZ * WSZ];

// ---------------------------------------------------------------------------
// Kernel 1: boundary (3x3 morph gradient, edge padding) + exact 1D row
// distance via outward early-exit search. One block per (b,h) row.
// Block 0 zeroes the output scalar (poisoned by the harness).
// ---------------------------------------------------------------------------
__global__ __launch_bounds__(256) void rowdist_kernel(const int* __restrict__ targets,
                                                      float* __restrict__ out) {
    const int blk = blockIdx.x;
    const int b = blk >> 8;
    const int h = blk & 255;
    const int j = threadIdx.x;

    if (blk == 0 && j == 0) out[0] = 0.0f;

    __shared__ int vmx[WSZ];
    __shared__ int vmn[WSZ];
    __shared__ int bnd[WSZ];

    const int* tb = targets + b * HW;
    const int hm = (h > 0)   ? h - 1 : 0;      // edge padding == clamp
    const int hp = (h < 255) ? h + 1 : 255;

    const int a = tb[hm * WSZ + j];
    const int c = tb[h  * WSZ + j];
    const int e = tb[hp * WSZ + j];
    vmx[j] = max(a, max(c, e));
    vmn[j] = min(a, min(c, e));
    __syncthreads();

    const int jm = (j > 0)   ? j - 1 : 0;
    const int jp = (j < 255) ? j + 1 : 255;
    const int mx = max(vmx[jm], max(vmx[j], vmx[jp]));
    const int mn = min(vmn[jm], min(vmn[j], vmn[jp]));

    bnd[j] = (mx != mn);
    __syncthreads();

    float d = INF_F;
    if (bnd[j]) {
        d = 0.0f;
    } else {
        for (int s = 1; s < WSZ; ++s) {
            const int lo = j - s;
            const int hi = j + s;
            if ((lo >= 0 && bnd[lo]) || (hi < WSZ && bnd[hi])) { d = (float)s; break; }
        }
    }
    g_g2[(b * HSZ + h) * WSZ + j] = d * d;
}

// ---------------------------------------------------------------------------
// Kernel 2: streaming fused column-EDT + cross-entropy + weighted mean.
// Thread = 2 consecutive pixels. KEY CHANGE vs R6: all 19 float2 channel
// loads are issued up-front into a register array (no occupancy clamp, so
// ptxas has ~70-80 regs to batch them) -> per-warp bytes-in-flight ~4.9KB,
// covering the 577-cycle DRAM latency that both previous variants exposed.
// The L2-resident EDT work overlaps the in-flight DRAM loads.
// ---------------------------------------------------------------------------
__global__ __launch_bounds__(256) void ce_kernel(const float* __restrict__ x,
                                                 const int* __restrict__ targets,
                                                 float* __restrict__ out) {
    const int tid  = blockIdx.x * 256 + threadIdx.x;
    const int base = tid << 1;                 // global pixel index
    const int b    = base >> 16;
    const int off  = base & 0xFFFF;            // i*256 + j within image
    const int i    = off >> 8;

    const float* xb = x + (long)b * (CSZ * HW) + off;

    // ---- issue ALL channel loads first (batched -> high MLP) ----
    float2 v[CSZ];
    #pragma unroll
    for (int c = 0; c < CSZ; c++) v[c] = *(const float2*)(xb + c * HW);

    const int2 tg = *(const int2*)(targets + (b << 16) + off);

    // ---- column EDT for 2 pixels (L2-resident; overlaps DRAM loads) ----
    const float* g2b = g_g2 + (b << 16);
    float2 bst = *(const float2*)(g2b + off);
    float bmax = fmaxf(bst.x, bst.y);
    for (int dlt = 1; dlt < HSZ; ++dlt) {
        const float dd2 = (float)(dlt * dlt);
        if (dd2 >= bmax) break;                // exact: candidates at dlt >= dlt^2
        const int up = i - dlt;
        const int dn = i + dlt;
        if (up >= 0) {
            const float2 g = *(const float2*)(g2b + off - (dlt << 8));
            bst.x = fminf(bst.x, dd2 + g.x);
            bst.y = fminf(bst.y, dd2 + g.y);
        }
        if (dn < HSZ) {
            const float2 g = *(const float2*)(g2b + off + (dlt << 8));
            bst.x = fminf(bst.x, dd2 + g.x);
            bst.y = fminf(bst.y, dd2 + g.y);
        }
        bmax = fmaxf(bst.x, bst.y);
    }
    const float d0 = sqrtf(bst.x), d1 = sqrtf(bst.y);
    // d > 1e5 <=> image has no boundary at all; else d <= sqrt(2)*255
    const float w0 = (d0 > 1.0e5f) ? 1.0f : __expf(-0.2f * d0);
    const float w1 = (d1 > 1.0e5f) ? 1.0f : __expf(-0.2f * d1);

    // ---- cross-entropy: single pass, no max subtraction (logits ~N(0,1)) ----
    float e0a = 0.0f, e0b = 0.0f, e1a = 0.0f, e1b = 0.0f;
    float sel0 = 0.0f, sel1 = 0.0f;
    #pragma unroll
    for (int c = 0; c < CSZ; c += 2) {
        e0a += __expf(v[c].x);
        e1a += __expf(v[c].y);
        if (c + 1 < CSZ) {
            e0b += __expf(v[c + 1].x);
            e1b += __expf(v[c + 1].y);
        }
    }
    #pragma unroll
    for (int c = 0; c < CSZ; c++) {
        if (c == tg.x) sel0 = v[c].x;          // predicated selects
        if (c == tg.y) sel1 = v[c].y;
    }

    float acc = (__logf(e0a + e0b) - sel0) * w0
              + (__logf(e1a + e1b) - sel1) * w1;

    // ---- block reduce (8 warps) + one atomic per block ----
    #pragma unroll
    for (int o = 16; o > 0; o >>= 1) acc += __shfl_down_sync(0xFFFFFFFFu, acc, o);

    __shared__ float red[8];
    const int t = threadIdx.x;
    if ((t & 31) == 0) red[t >> 5] = acc;
    __syncthreads();
    if (t < 32) {
        float r = (t < 8) ? red[t] : 0.0f;
        #pragma unroll
        for (int o = 4; o > 0; o >>= 1) r += __shfl_down_sync(0xFFFFFFFFu, r, o);
        if (t == 0) {
            const float inv_n = 1.0f / (float)(BSZ * HW);
            atomicAdd(out, r * inv_n);
        }
    }
}

// ---------------------------------------------------------------------------
extern "C" void kernel_launch(void* const* d_in, const int* in_sizes, int n_in,
                              void* d_out, int out_size) {
    const float* inputs  = (const float*)d_in[0];   // [8,19,256,256] fp32
    const int*   targets = (const int*)  d_in[1];   // [8,256,256] int32
    float*       out     = (float*)d_out;           // scalar

    rowdist_kernel<<<BSZ * HSZ, WSZ>>>(targets, out);
    ce_kernel<<<(BSZ * HW) / (2 * 256), 256>>>(inputs, targets, out);
}

// round 14
// speedup vs baseline: 1.1380x; 1.1380x over previous
#include <cuda_runtime.h>
#include <cuda_bf16.h>
#include <cstdint>

#define BSZ 8
#define CSZ 19
#define HSZ 256
#define WSZ 256
#define HW  (HSZ * WSZ)
#define INF_F 1.0e6f
#define TILE 1024          // pixels per block
#define NBUF 11            // smem channel buffers (44KB < 48KB static limit)

// 2 MB scratch for squared per-row distances  [B][H][W]
__device__ float g_g2[BSZ * HSZ * WSZ];

#define CP_ASYNC16(dst, src) \
    asm volatile("cp.async.cg.shared.global [%0], [%1], 16;" :: "r"(dst), "l"(src) : "memory")
#define CP_COMMIT() asm volatile("cp.async.commit_group;" ::: "memory")
#define CP_WAIT10() asm volatile("cp.async.wait_group 10;" ::: "memory")

// ---------------------------------------------------------------------------
// Kernel 1: boundary (3x3 morph gradient, edge padding) + exact 1D row
// distance via outward early-exit search. One block per (b,h) row.
// Block 0 zeroes the output scalar (poisoned by the harness).
// ---------------------------------------------------------------------------
__global__ __launch_bounds__(256) void rowdist_kernel(const int* __restrict__ targets,
                                                      float* __restrict__ out) {
    const int blk = blockIdx.x;
    const int b = blk >> 8;
    const int h = blk & 255;
    const int j = threadIdx.x;

    if (blk == 0 && j == 0) out[0] = 0.0f;

    __shared__ int vmx[WSZ];
    __shared__ int vmn[WSZ];
    __shared__ int bnd[WSZ];

    const int* tb = targets + b * HW;
    const int hm = (h > 0)   ? h - 1 : 0;      // edge padding == clamp
    const int hp = (h < 255) ? h + 1 : 255;

    const int a = tb[hm * WSZ + j];
    const int c = tb[h  * WSZ + j];
    const int e = tb[hp * WSZ + j];
    vmx[j] = max(a, max(c, e));
    vmn[j] = min(a, min(c, e));
    __syncthreads();

    const int jm = (j > 0)   ? j - 1 : 0;
    const int jp = (j < 255) ? j + 1 : 255;
    const int mx = max(vmx[jm], max(vmx[j], vmx[jp]));
    const int mn = min(vmn[jm], min(vmn[j], vmn[jp]));

    bnd[j] = (mx != mn);
    __syncthreads();

    float d = INF_F;
    if (bnd[j]) {
        d = 0.0f;
    } else {
        for (int s = 1; s < WSZ; ++s) {
            const int lo = j - s;
            const int hi = j + s;
            if ((lo >= 0 && bnd[lo]) || (hi < WSZ && bnd[hi])) { d = (float)s; break; }
        }
    }
    g_g2[(b * HSZ + h) * WSZ + j] = d * d;
}

// ---------------------------------------------------------------------------
// Kernel 2: cp.async-pipelined column-EDT + cross-entropy + weighted mean.
// Thread owns 4 consecutive pixels (16B per channel). Channel tiles are
// staged global->smem with cp.async (no register residency): 11 buffers,
// one commit group per channel, rolling refill. Pipeline depth is bounded
// by smem (44KB in flight per block, all 512 blocks co-resident), not by
// registers — the register-MLP variants could not achieve this.
// Grid: 512 blocks x 256 threads.
// ---------------------------------------------------------------------------
__global__ __launch_bounds__(256) void ce_kernel(const float* __restrict__ x,
                                                 const int* __restrict__ targets,
                                                 float* __restrict__ out) {
    __shared__ float buf[NBUF][TILE];
    __shared__ float red[8];

    const int t    = threadIdx.x;
    const int base = blockIdx.x * TILE;        // global pixel base of this block
    const int b    = base >> 16;
    const int px   = (base & 0xFFFF) + (t << 2);  // thread's first pixel in image
    const int i    = px >> 8;                  // row

    const float* xb = x + (long)b * (CSZ * HW);
    const unsigned int sb = (unsigned int)__cvta_generic_to_shared(buf);
    const unsigned int sd = sb + (t << 4);     // this thread's 16B slot offset

    // ---- prologue: fill all NBUF pipeline stages ----
    #pragma unroll
    for (int c = 0; c < NBUF; c++) {
        CP_ASYNC16(sd + c * (TILE * 4), xb + c * HW + px);
        CP_COMMIT();
    }

    // ---- overlapped with loads: targets, target-logit gathers, EDT ----
    const int4 tg = *(const int4*)(targets + (b << 16) + px);
    const float s0 = xb[tg.x * HW + px];
    const float s1 = xb[tg.y * HW + px + 1];
    const float s2 = xb[tg.z * HW + px + 2];
    const float s3 = xb[tg.w * HW + px + 3];

    const float* g2b = g_g2 + (b << 16);
    float4 bst = *(const float4*)(g2b + px);
    float bmax = fmaxf(fmaxf(bst.x, bst.y), fmaxf(bst.z, bst.w));
    for (int dlt = 1; dlt < HSZ; ++dlt) {
        const float dd2 = (float)(dlt * dlt);
        if (dd2 >= bmax) break;                // exact: candidates at dlt >= dlt^2
        const int up = i - dlt;
        const int dn = i + dlt;
        if (up >= 0) {
            const float4 g = *(const float4*)(g2b + px - (dlt << 8));
            bst.x = fminf(bst.x, dd2 + g.x);
            bst.y = fminf(bst.y, dd2 + g.y);
            bst.z = fminf(bst.z, dd2 + g.z);
            bst.w = fminf(bst.w, dd2 + g.w);
        }
        if (dn < HSZ) {
            const float4 g = *(const float4*)(g2b + px + (dlt << 8));
            bst.x = fminf(bst.x, dd2 + g.x);
            bst.y = fminf(bst.y, dd2 + g.y);
            bst.z = fminf(bst.z, dd2 + g.z);
            bst.w = fminf(bst.w, dd2 + g.w);
        }
        bmax = fmaxf(fmaxf(bst.x, bst.y), fmaxf(bst.z, bst.w));
    }
    const float d0 = sqrtf(bst.x), d1 = sqrtf(bst.y);
    const float d2 = sqrtf(bst.z), d3 = sqrtf(bst.w);
    // d > 1e5 <=> image has no boundary (w==1 everywhere); else d <= 361
    const float w0 = (d0 > 1.0e5f) ? 1.0f : __expf(-0.2f * d0);
    const float w1 = (d1 > 1.0e5f) ? 1.0f : __expf(-0.2f * d1);
    const float w2 = (d2 > 1.0e5f) ? 1.0f : __expf(-0.2f * d2);
    const float w3 = (d3 > 1.0e5f) ? 1.0f : __expf(-0.2f * d3);

    // ---- rolling consume/refill over the 19 channels ----
    float e0 = 0.0f, e1 = 0.0f, e2 = 0.0f, e3 = 0.0f;
    #pragma unroll
    for (int c = 0; c < CSZ; c++) {
        CP_WAIT10();                            // group c complete (in-order)
        const int slot = c % NBUF;
        const float4 v = *(const float4*)&buf[slot][t << 2];  // own 16B: no sync needed
        if (c + NBUF < CSZ) {                   // refill the slot just consumed
            CP_ASYNC16(sd + slot * (TILE * 4), xb + (c + NBUF) * HW + px);
            CP_COMMIT();
        } else {
            CP_COMMIT();                        // dummy: keep wait distance constant
        }
        e0 += __expf(v.x);
        e1 += __expf(v.y);
        e2 += __expf(v.z);
        e3 += __expf(v.w);
    }

    float acc = (__logf(e0) - s0) * w0
              + (__logf(e1) - s1) * w1
              + (__logf(e2) - s2) * w2
              + (__logf(e3) - s3) * w3;

    // ---- block reduce (8 warps) + one atomic per block ----
    #pragma unroll
    for (int o = 16; o > 0; o >>= 1) acc += __shfl_down_sync(0xFFFFFFFFu, acc, o);

    if ((t & 31) == 0) red[t >> 5] = acc;
    __syncthreads();
    if (t < 32) {
        float r = (t < 8) ? red[t] : 0.0f;
        #pragma unroll
        for (int o = 4; o > 0; o >>= 1) r += __shfl_down_sync(0xFFFFFFFFu, r, o);
        if (t == 0) {
            const float inv_n = 1.0f / (float)(BSZ * HW);
            atomicAdd(out, r * inv_n);
        }
    }
}

// ---------------------------------------------------------------------------
extern "C" void kernel_launch(void* const* d_in, const int* in_sizes, int n_in,
                              void* d_out, int out_size) {
    const float* inputs  = (const float*)d_in[0];   // [8,19,256,256] fp32
    const int*   targets = (const int*)  d_in[1];   // [8,256,256] int32
    float*       out     = (float*)d_out;           // scalar

    rowdist_kernel<<<BSZ * HSZ, WSZ>>>(targets, out);
    ce_kernel<<<(BSZ * HW) / TILE, 256>>>(inputs, targets, out);
}

// round 15
// speedup vs baseline: 1.6096x; 1.4144x over previous
#include <cuda_runtime.h>
#include <cuda_bf16.h>
#include <cstdint>

#define BSZ 8
#define CSZ 19
#define HSZ 256
#define WSZ 256
#define HW  (HSZ * WSZ)
#define NBLK 1024          // grid size (fixed)

__device__ float        g_part[NBLK];
__device__ unsigned int g_cnt = 0;   // self-resetting via atomicInc wrap

// ---------------------------------------------------------------------------
// 3x3 morphological-gradient boundary test at (i,j), edge-clamped.
// targets is 2MB -> L2-resident; these loads are cheap.
// ---------------------------------------------------------------------------
__device__ __forceinline__ bool is_bnd(const int* __restrict__ tb, int i, int j) {
    const int* r0 = tb + max(i - 1, 0) * WSZ;
    const int* r1 = tb + i * WSZ;
    const int* r2 = tb + min(i + 1, HSZ - 1) * WSZ;
    const int jm = max(j - 1, 0), jp = min(j + 1, WSZ - 1);
    const int a = r0[jm], b = r0[j], c = r0[jp];
    const int d = r1[jm], e = r1[j], f = r1[jp];
    const int g = r2[jm], h = r2[j], k = r2[jp];
    const int mx = max(max(max(a, b), max(c, d)), max(max(e, f), max(g, max(h, k))));
    const int mn = min(min(min(a, b), min(c, d)), min(min(e, f), min(g, min(h, k))));
    return mx != mn;
}

// ---------------------------------------------------------------------------
// Exact 2D EDT fallback for the (vanishingly rare) non-boundary pixel:
// d^2 = min over rows k of (i-k)^2 + rowdist(k,j)^2, evaluated by outward
// search with pruning (dlt^2 >= best, s^2 >= best - dlt^2). Exact for any
// input; cost is data-dependent and tiny on dense-random labels.
// Returns 1e6 (INF) when the image has no boundary at all (matches ref).
// ---------------------------------------------------------------------------
__device__ __noinline__ float edt_fallback(const int* __restrict__ tb, int i, int j) {
    float best = 1.0e12f;                       // INF^2
    for (int dlt = 0; dlt < HSZ; ++dlt) {
        const float dd2 = (float)(dlt * dlt);
        if (dd2 >= best) break;
        #pragma unroll
        for (int pass = 0; pass < 2; ++pass) {
            if (dlt == 0 && pass == 1) break;
            const int k = pass ? i + dlt : i - dlt;
            if (k < 0 || k >= HSZ) continue;
            for (int s = 0; s < WSZ; ++s) {
                const float cand = dd2 + (float)(s * s);
                if (cand >= best) break;
                const int lo = j - s, hi = j + s;
                bool f = false;
                if (lo >= 0  && is_bnd(tb, k, lo)) f = true;
                if (!f && hi < WSZ && is_bnd(tb, k, hi)) f = true;
                if (f) { best = cand; break; }
            }
        }
    }
    return sqrtf(best);
}

// ---------------------------------------------------------------------------
// Fused kernel: boundary weight + cross-entropy + full reduction.
// Thread = 4 consecutive pixels (float4 channel loads, R5 structure — the
// best-measured memory configuration). Boundary weight computed inline from
// targets (no scratch, no second kernel). Last block (atomicInc-wrap ticket,
// self-resetting across graph replays) reduces the per-block partials and
// writes the scalar output — no zero-kernel, no atomics on d_out.
// Grid: 1024 blocks x 128 threads.
// ---------------------------------------------------------------------------
__global__ __launch_bounds__(128) void fused_kernel(const float* __restrict__ x,
                                                    const int* __restrict__ targets,
                                                    float* __restrict__ out) {
    const int t    = threadIdx.x;
    const int tid  = blockIdx.x * 128 + t;
    const int base = tid << 2;                  // first pixel (global)
    const int b    = base >> 16;
    const int off  = base & 0xFFFF;             // i*256 + j within image
    const int i    = off >> 8;
    const int j    = off & 255;

    const int*   tb = targets + (b << 16);
    const float* xb = x + (long)b * (CSZ * HW) + off;

    // ---- boundary weights for 4 pixels (shared 3x4+2 column window) ----
    const int* r0 = tb + max(i - 1, 0) * WSZ;
    const int* r1 = tb + i * WSZ;
    const int* r2 = tb + min(i + 1, HSZ - 1) * WSZ;

    int cmx[6], cmn[6];
    #pragma unroll
    for (int q = 0; q < 6; q++) {
        int c = j - 1 + q;
        c = max(c, 0); c = min(c, WSZ - 1);
        const int a = r0[c], d = r1[c], e = r2[c];
        cmx[q] = max(a, max(d, e));
        cmn[q] = min(a, min(d, e));
    }
    bool bb[4];
    #pragma unroll
    for (int p = 0; p < 4; p++) {
        const int mx = max(cmx[p], max(cmx[p + 1], cmx[p + 2]));
        const int mn = min(cmn[p], min(cmn[p + 1], cmn[p + 2]));
        bb[p] = (mx != mn);
    }
    float w[4];
    #pragma unroll
    for (int p = 0; p < 4; p++) w[p] = 1.0f;    // boundary pixel -> d=0 -> w=1
    if (!(bb[0] && bb[1] && bb[2] && bb[3])) {  // rare on dense-random labels
        #pragma unroll
        for (int p = 0; p < 4; p++) if (!bb[p]) {
            const float d = edt_fallback(tb, i, j + p);
            // d > 1e5 <=> no boundary anywhere in image -> w = 1 (matches ref)
            w[p] = (d > 1.0e5f) ? 1.0f : __expf(-0.2f * d);
        }
    }

    // ---- target logits (gather; lines shared with the streaming loop) ----
    const int4 tg = *(const int4*)(tb + off);
    const float s0 = xb[tg.x * HW + 0];
    const float s1 = xb[tg.y * HW + 1];
    const float s2 = xb[tg.z * HW + 2];
    const float s3 = xb[tg.w * HW + 3];

    // ---- cross-entropy: single pass, no max subtraction (logits ~N(0,1)) ----
    float e0 = 0.0f, e1 = 0.0f, e2 = 0.0f, e3 = 0.0f;
    #pragma unroll
    for (int c = 0; c < CSZ; c++) {
        const float4 v = *(const float4*)(xb + c * HW);
        e0 += __expf(v.x);
        e1 += __expf(v.y);
        e2 += __expf(v.z);
        e3 += __expf(v.w);
    }

    float acc = (__logf(e0) - s0) * w[0]
              + (__logf(e1) - s1) * w[1]
              + (__logf(e2) - s2) * w[2]
              + (__logf(e3) - s3) * w[3];

    // ---- block reduce (4 warps) ----
    #pragma unroll
    for (int o = 16; o > 0; o >>= 1) acc += __shfl_down_sync(0xFFFFFFFFu, acc, o);

    __shared__ float red[4];
    __shared__ bool  amlast;
    if ((t & 31) == 0) red[t >> 5] = acc;
    __syncthreads();
    if (t == 0) {
        const float part = red[0] + red[1] + red[2] + red[3];
        g_part[blockIdx.x] = part;
        __threadfence();
        const unsigned int old = atomicInc(&g_cnt, NBLK - 1);  // wraps to 0 after last
        amlast = (old == NBLK - 1);
    }
    __syncthreads();

    // ---- last block reduces all partials and writes the output ----
    if (amlast) {
        float r = 0.0f;
        #pragma unroll
        for (int q = 0; q < NBLK / 128; q++) r += g_part[t + q * 128];
        #pragma unroll
        for (int o = 16; o > 0; o >>= 1) r += __shfl_down_sync(0xFFFFFFFFu, r, o);
        if ((t & 31) == 0) red[t >> 5] = r;
        __syncthreads();
        if (t == 0) {
            const float inv_n = 1.0f / (float)(BSZ * HW);
            out[0] = (red[0] + red[1] + red[2] + red[3]) * inv_n;
        }
    }
}

// ---------------------------------------------------------------------------
extern "C" void kernel_launch(void* const* d_in, const int* in_sizes, int n_in,
                              void* d_out, int out_size) {
    const float* inputs  = (const float*)d_in[0];   // [8,19,256,256] fp32
    const int*   targets = (const int*)  d_in[1];   // [8,256,256] int32
    float*       out     = (float*)d_out;           // scalar

    fused_kernel<<<NBLK, 128>>>(inputs, targets, out);
}